// round 7
// baseline (speedup 1.0000x reference)
#include <cuda_runtime.h>
#include <math.h>

#define CHUNKS 8
#define MAXB   1024
#define MAXC   (MAXB * CHUNKS)
#define NTHR   256

// Per-(row,chunk) partials.
__device__ float g_s[3 * MAXC];   // sum exp(v) per stream
__device__ float g_a[4 * MAXC];   // a0,a1,a2 (dot with x), ax (sum x)
__device__ float g_lat[3 * MAXB]; // per-row k1, k2, bw (chunk 0)
__device__ unsigned int g_count;  // arrival counter

__device__ __forceinline__ unsigned smem_addr(const void* p) {
    unsigned a;
    asm("{ .reg .u64 t; cvta.to.shared.u64 t, %1; cvt.u32.u64 %0, t; }"
        : "=r"(a) : "l"(p));
    return a;
}

__device__ __forceinline__ void bulk_g2s(unsigned dst, const void* src,
                                         unsigned bytes, unsigned mbar) {
    asm volatile(
        "cp.async.bulk.shared::cluster.global.mbarrier::complete_tx::bytes "
        "[%0], [%1], %2, [%3];"
        :: "r"(dst), "l"(src), "r"(bytes), "r"(mbar) : "memory");
}

__device__ __forceinline__ void mbar_wait(unsigned addr, unsigned phase) {
    asm volatile(
        "{\n\t"
        ".reg .pred P;\n\t"
        "W%=:\n\t"
        "mbarrier.try_wait.parity.acquire.cta.shared::cta.b64 P, [%0], %1, 0x989680;\n\t"
        "@P bra D%=;\n\t"
        "bra W%=;\n\t"
        "D%=:\n\t"
        "}"
        :: "r"(addr), "r"(phase) : "memory");
}

__device__ __forceinline__ float exp4(float4 v) {
    return (__expf(v.x) + __expf(v.y)) + (__expf(v.z) + __expf(v.w));
}

__global__ __launch_bounds__(NTHR, 5)
void fused_loss_kernel(const float* __restrict__ recon_x,
                       const float* __restrict__ x,
                       const float* __restrict__ lt,
                       const float* __restrict__ lr,
                       const float* __restrict__ mu,
                       const float* __restrict__ lv,
                       const float* __restrict__ pmu,
                       const float* __restrict__ plv,
                       float* __restrict__ out,
                       int B, int N, int D, int cf)   // cf = floats per chunk (mult of 4)
{
    extern __shared__ float smem[];            // 4*cf floats: [rx | x | lt | lr]
    __shared__ unsigned long long mbar;
    __shared__ bool isLast;

    const int blk = blockIdx.x;
    const int b   = blk / CHUNKS;
    const int c   = blk % CHUNKS;
    const int tid = threadIdx.x;
    const size_t rowN = (size_t)b * N;
    const size_t rowD = (size_t)b * D;
    const size_t off  = rowN + (size_t)c * cf;

    float* s_r = smem;
    float* s_x = smem + cf;
    float* s_t = smem + 2 * cf;
    float* s_l = smem + 3 * cf;
    const unsigned mb = smem_addr(&mbar);
    const unsigned bytes = (unsigned)cf * 4u;

    if (tid == 0) {
        asm volatile("mbarrier.init.shared.b64 [%0], 1;" :: "r"(mb) : "memory");
        asm volatile("fence.proxy.async.shared::cta;" ::: "memory");
    }
    __syncthreads();
    if (tid == 0) {
        asm volatile("mbarrier.arrive.expect_tx.shared.b64 _, [%0], %1;"
                     :: "r"(mb), "r"(4u * bytes) : "memory");
        bulk_g2s(smem_addr(s_r), recon_x + off, bytes, mb);
        bulk_g2s(smem_addr(s_x), x       + off, bytes, mb);
        bulk_g2s(smem_addr(s_t), lt      + off, bytes, mb);
        bulk_g2s(smem_addr(s_l), lr      + off, bytes, mb);
    }

    // ---- latent row (chunk 0 only) while TMA streams ----
    float k1 = 0.f, k2 = 0.f, bw = 0.f;
    if (c == 0) {
        for (int j = tid; j < D; j += NTHR) {
            float lvv  = lv[rowD + j];
            float plvv = plv[rowD + j];
            float e1 = __expf(lvv);
            float e2 = __expf(plvv);
            float cc = __expf(0.5f * (lvv + plvv));     // sqrt(e1*e2)
            k1 += 1.0f + lvv  - e1;
            k2 += 1.0f + plvv - e2;
            float dm = mu[rowD + j] - pmu[rowD + j];
            bw = fmaf(dm, dm, bw) + e1 + e2 - 2.0f * cc;
        }
    }

    float s0 = 0.f, s1 = 0.f, s2 = 0.f;
    float a0 = 0.f, a1 = 0.f, a2 = 0.f, ax = 0.f;

    // scalar tail of the row (N - CHUNKS*cf leftovers), last chunk, from GMEM
    if (c == CHUNKS - 1) {
        for (int j = CHUNKS * cf + tid; j < N; j += NTHR) {
            float v0 = recon_x[rowN + j];
            float vx = x[rowN + j];
            float v1 = lt[rowN + j];
            float v2 = lr[rowN + j];
            s0 += __expf(v0); s1 += __expf(v1); s2 += __expf(v2);
            a0 = fmaf(v0, vx, a0); a1 = fmaf(v1, vx, a1); a2 = fmaf(v2, vx, a2);
            ax += vx;
        }
    }

    // ---- wait for the 40KB job, then compute out of smem ----
    mbar_wait(mb, 0);

    const float4* r4 = (const float4*)s_r;
    const float4* x4 = (const float4*)s_x;
    const float4* t4 = (const float4*)s_t;
    const float4* l4 = (const float4*)s_l;
    const int q4 = cf >> 2;

    for (int i = tid; i < q4; i += NTHR) {
        float4 vr = r4[i];
        float4 vx = x4[i];
        float4 vt = t4[i];
        float4 vl = l4[i];

        s0 += exp4(vr);
        s1 += exp4(vt);
        s2 += exp4(vl);

        a0 = fmaf(vr.x, vx.x, fmaf(vr.y, vx.y, fmaf(vr.z, vx.z, fmaf(vr.w, vx.w, a0))));
        a1 = fmaf(vt.x, vx.x, fmaf(vt.y, vx.y, fmaf(vt.z, vx.z, fmaf(vt.w, vx.w, a1))));
        a2 = fmaf(vl.x, vx.x, fmaf(vl.y, vx.y, fmaf(vl.z, vx.z, fmaf(vl.w, vx.w, a2))));
        ax += (vx.x + vx.y) + (vx.z + vx.w);
    }

    // ---- block reduction of 10 plain sums ----
    const unsigned FULL = 0xFFFFFFFFu;
    #pragma unroll
    for (int o = 16; o; o >>= 1) {
        s0 += __shfl_xor_sync(FULL, s0, o);
        s1 += __shfl_xor_sync(FULL, s1, o);
        s2 += __shfl_xor_sync(FULL, s2, o);
        a0 += __shfl_xor_sync(FULL, a0, o);
        a1 += __shfl_xor_sync(FULL, a1, o);
        a2 += __shfl_xor_sync(FULL, a2, o);
        ax += __shfl_xor_sync(FULL, ax, o);
        k1 += __shfl_xor_sync(FULL, k1, o);
        k2 += __shfl_xor_sync(FULL, k2, o);
        bw += __shfl_xor_sync(FULL, bw, o);
    }

    __shared__ float sh[8][10];
    const int warp = tid >> 5;
    const int lane = tid & 31;
    if (lane == 0) {
        sh[warp][0] = s0; sh[warp][1] = s1; sh[warp][2] = s2;
        sh[warp][3] = a0; sh[warp][4] = a1; sh[warp][5] = a2;
        sh[warp][6] = ax; sh[warp][7] = k1; sh[warp][8] = k2; sh[warp][9] = bw;
    }
    __syncthreads();

    if (warp == 0) {
        if (lane < 8) {
            s0 = sh[lane][0]; s1 = sh[lane][1]; s2 = sh[lane][2];
            a0 = sh[lane][3]; a1 = sh[lane][4]; a2 = sh[lane][5];
            ax = sh[lane][6]; k1 = sh[lane][7]; k2 = sh[lane][8]; bw = sh[lane][9];
        } else {
            s0 = s1 = s2 = a0 = a1 = a2 = ax = k1 = k2 = bw = 0.f;
        }
        #pragma unroll
        for (int o = 4; o; o >>= 1) {
            s0 += __shfl_xor_sync(FULL, s0, o);
            s1 += __shfl_xor_sync(FULL, s1, o);
            s2 += __shfl_xor_sync(FULL, s2, o);
            a0 += __shfl_xor_sync(FULL, a0, o);
            a1 += __shfl_xor_sync(FULL, a1, o);
            a2 += __shfl_xor_sync(FULL, a2, o);
            ax += __shfl_xor_sync(FULL, ax, o);
            k1 += __shfl_xor_sync(FULL, k1, o);
            k2 += __shfl_xor_sync(FULL, k2, o);
            bw += __shfl_xor_sync(FULL, bw, o);
        }
        if (lane == 0) {
            g_s[0 * MAXC + blk] = s0;
            g_s[1 * MAXC + blk] = s1;
            g_s[2 * MAXC + blk] = s2;
            g_a[0 * MAXC + blk] = a0;
            g_a[1 * MAXC + blk] = a1;
            g_a[2 * MAXC + blk] = a2;
            g_a[3 * MAXC + blk] = ax;
            if (c == 0) {
                g_lat[0 * MAXB + b] = k1;
                g_lat[1 * MAXB + b] = k2;
                g_lat[2 * MAXB + b] = bw;
            }
        }
    }

    // ---- last-block-done: finalize inline ----
    __threadfence();
    __syncthreads();
    if (tid == 0) {
        unsigned int old = atomicAdd(&g_count, 1u);
        isLast = (old == gridDim.x - 1);
    }
    __syncthreads();
    if (!isLast) return;

    __threadfence();

    float t0 = 0.f, t1 = 0.f, t2 = 0.f, t3 = 0.f, t4v = 0.f, t5 = 0.f;
    for (int r = tid; r < B; r += NTHR) {
        float rs0 = 0.f, rs1 = 0.f, rs2 = 0.f;
        float ra0 = 0.f, ra1 = 0.f, ra2 = 0.f, rax = 0.f;
        #pragma unroll
        for (int cc = 0; cc < CHUNKS; cc++) {
            int idx = r * CHUNKS + cc;
            rs0 += g_s[0 * MAXC + idx];
            rs1 += g_s[1 * MAXC + idx];
            rs2 += g_s[2 * MAXC + idx];
            ra0 += g_a[0 * MAXC + idx];
            ra1 += g_a[1 * MAXC + idx];
            ra2 += g_a[2 * MAXC + idx];
            rax += g_a[3 * MAXC + idx];
        }
        t0 += ra0 - logf(rs0) * rax;  // merged
        t1 += ra1 - logf(rs1) * rax;  // text
        t2 += ra2 - logf(rs2) * rax;  // rec
        t3  += g_lat[0 * MAXB + r];
        t4v += g_lat[1 * MAXB + r];
        t5  += g_lat[2 * MAXB + r];
    }

    #pragma unroll
    for (int o = 16; o; o >>= 1) {
        t0  += __shfl_xor_sync(FULL, t0,  o);
        t1  += __shfl_xor_sync(FULL, t1,  o);
        t2  += __shfl_xor_sync(FULL, t2,  o);
        t3  += __shfl_xor_sync(FULL, t3,  o);
        t4v += __shfl_xor_sync(FULL, t4v, o);
        t5  += __shfl_xor_sync(FULL, t5,  o);
    }
    __shared__ float sh2[8][6];
    if (lane == 0) {
        sh2[warp][0] = t0; sh2[warp][1] = t1; sh2[warp][2] = t2;
        sh2[warp][3] = t3; sh2[warp][4] = t4v; sh2[warp][5] = t5;
    }
    __syncthreads();
    if (tid == 0) {
        float u[6] = {0.f, 0.f, 0.f, 0.f, 0.f, 0.f};
        for (int w = 0; w < 8; w++) {
            u[0] += sh2[w][0]; u[1] += sh2[w][1]; u[2] += sh2[w][2];
            u[3] += sh2[w][3]; u[4] += sh2[w][4]; u[5] += sh2[w][5];
        }
        float invBN = 1.0f / ((float)B * (float)N);
        float bce_m = -u[0] * invBN;
        float bce_t = -u[1] * invBN;
        float bce_r = -u[2] * invBN;
        float BCE = (bce_m + bce_t + bce_r) * (1.0f / 3.0f);
        float invBD = 1.0f / ((float)B * (float)D);
        float kld1 = -0.5f * u[3] * invBD;
        float kld2 = -0.5f * u[4] * invBD;
        float W = u[5] / (float)B;
        out[0] = BCE + 0.5f * (kld1 + kld2) + W;  // l (anneal=1, epsilon=1)
        out[1] = BCE;
        out[2] = W;
        out[3] = bce_r;
        out[4] = bce_t;
        out[5] = bce_m;
        g_count = 0;  // reset for next graph replay
    }
}

extern "C" void kernel_launch(void* const* d_in, const int* in_sizes, int n_in,
                              void* d_out, int out_size) {
    const float* recon_x = (const float*)d_in[0];
    const float* x       = (const float*)d_in[1];
    const float* mu      = (const float*)d_in[2];
    const float* logvar  = (const float*)d_in[3];
    const float* lt      = (const float*)d_in[4];
    const float* lr      = (const float*)d_in[5];
    const float* pmu     = (const float*)d_in[6];
    const float* plv     = (const float*)d_in[7];

    const int D = 400;
    const int B = in_sizes[2] / D;
    const int N = in_sizes[0] / B;
    const int cf = (N / CHUNKS) & ~3;        // floats per chunk, 16B-multiple
    const size_t smemBytes = (size_t)4 * cf * sizeof(float);  // 40000B for N=20000

    fused_loss_kernel<<<B * CHUNKS, NTHR, smemBytes>>>(
        recon_x, x, lt, lr, mu, logvar, pmu, plv,
        (float*)d_out, B, N, D, cf);
}